// round 7
// baseline (speedup 1.0000x reference)
#include <cuda_runtime.h>
#include <mma.h>
#include <cstdint>

using namespace nvcuda;

#define FULLM 0xFFFFFFFFu
static constexpr int NDEPTH = 2;
static constexpr int NSIZE  = 1024;
static constexpr int NROWS  = 16384;
static constexpr int NCOEF  = 2046;   // sum of m for m=2..1024; factor m at offset m-2

__device__ float4 g_coef [NDEPTH * NCOEF];
__device__ float4 g_coefT[NDEPTH * NCOEF];
__device__ float  g_M[NSIZE * NSIZE];   // M[j][i] = network(e_j)[i], tf32-rounded

__global__ void repack_kernel(const float* __restrict__ abcd){
  int idx = blockIdx.x * blockDim.x + threadIdx.x;
  if (idx >= NDEPTH * NCOEF) return;
  int d  = idx / NCOEF;
  int qg = idx - d * NCOEF;
  int v  = qg + 2;
  int m  = 1 << (31 - __clz(v));
  int q  = v - m;
  int off = 4096 - 4 * m;
  int half = m >> 1;
  int ih = (q >= half) ? 1 : 0;
  int k  = q - ih * half;
  const float* base = abcd + (size_t)d * 4092 * 2;
  int i0 = off + ih * m + k;
  int i1 = i0 + half;
  float4 val = make_float4(base[2*i0], base[2*i0+1], base[2*i1], base[2*i1+1]);
  g_coef[idx] = val;
  int LB = m / 32;
  int tpos = (m >= 64) ? ((q & 31) * LB + (q >> 5)) : q;
  g_coefT[d * NCOEF + (m - 2) + tpos] = val;
}

__device__ __forceinline__ float mixf(float a, float b, float p){ return fmaf(p, b - a, a); }

template<int M>
__device__ __forceinline__ void perm_local(float* s, float* t, float p0, float p1, float p2){
#pragma unroll
  for (int g = 0; g < 32; g += M)
#pragma unroll
    for (int j = 0; j < M; j++){
      int sj = (j < M/2) ? 2*j : 2*j - M + 1;
      t[g+j] = mixf(s[g+j], s[g+sj], p0);
    }
#pragma unroll
  for (int g = 0; g < 32; g += M)
#pragma unroll
    for (int j = 0; j < M; j++){
      int pj = (j & (M/2)) | ((M/2 - 1) & ~j);
      s[g+j] = mixf(t[g+j], t[g+pj], (j < M/2) ? p1 : p2);
    }
}

template<int M>
__device__ __forceinline__ void perm_shfl_1(float* s, float* t, int lane, float p0, float p1, float p2){
  constexpr int LB = M/32;
  constexpr int T  = M/64;
  int Llow = lane & (LB - 1);
  int msb  = (Llow & T) ? 1 : 0;
  int slb  = (lane & ~(LB - 1)) | (2 * (Llow & (T - 1)));
  int sl0  = slb + msb;
  int sl1  = slb + 1 - msb;
  bool le  = (lane & 1) == 0;
#pragma unroll
  for (int k = 0; k < 16; k++){
    const int e = (2*k) & 31;
    float u1 = le ? s[e] : s[e|1];
    float v1 = (M == 64) ? u1 : __shfl_sync(FULLM, u1, sl0);
    float u2 = le ? s[e|1] : s[e];
    float v2 = __shfl_sync(FULLM, u2, sl1);
    float a = msb ? v2 : v1;
    float b = msb ? v1 : v2;
    t[k]    = mixf(s[k],    a, p0);
    t[k+16] = mixf(s[k+16], b, p0);
  }
  constexpr int RM = T - 1;
  float ps = (lane & T) ? p2 : p1;
  if (RM == 0){
#pragma unroll
    for (int r = 0; r < 16; r++){
      float x0 = t[r], x1 = t[31-r];
      s[r]    = mixf(x0, x1, ps);
      s[31-r] = mixf(x1, x0, ps);
    }
  } else {
#pragma unroll
    for (int r = 0; r < 32; r++){
      float pv = __shfl_xor_sync(FULLM, t[31-r], RM);
      s[r] = mixf(t[r], pv, ps);
    }
  }
}

__device__ __forceinline__ void perm_chain(float* s, float* t, int lane, const float* p){
  perm_local<4 >(s, t, p[0], p[1], p[2]);
  perm_local<8 >(s, t, p[0], p[1], p[2]);
  perm_local<16>(s, t, p[0], p[1], p[2]);
  perm_local<32>(s, t, p[0], p[1], p[2]);
  perm_shfl_1<64  >(s, t, lane, p[0], p[1], p[2]);
  perm_shfl_1<128 >(s, t, lane, p[0], p[1], p[2]);
  perm_shfl_1<256 >(s, t, lane, p[0], p[1], p[2]);
  perm_shfl_1<512 >(s, t, lane, p[0], p[1], p[2]);
  perm_shfl_1<1024>(s, t, lane, p[0], p[1], p[2]);
}

template<int M>
__device__ __forceinline__ void diag_local_ip(float* sx, float* sy, const float4* __restrict__ C){
#pragma unroll
  for (int q = 0; q < M/2; q++){
    float4 clo = __ldg(C + (M - 2) + q);
    float4 chi = __ldg(C + (M - 2) + q + M/2);
#pragma unroll
    for (int g = 0; g < 32; g += M){
      int lo = g + q, hi = lo + M/2;
      float ur = sx[lo], ui = sy[lo], vr = sx[hi], vi = sy[hi];
      sx[lo] = clo.x*ur - clo.y*ui + clo.z*vr - clo.w*vi;
      sy[lo] = clo.x*ui + clo.y*ur + clo.z*vi + clo.w*vr;
      sx[hi] = chi.x*ur - chi.y*ui + chi.z*vr - chi.w*vi;
      sy[hi] = chi.x*ui + chi.y*ur + chi.z*vi + chi.w*vr;
    }
  }
}

template<int M>
__device__ __forceinline__ void diag_shfl_ip(float* sx, float* sy, const float4* __restrict__ CT, int lane){
  constexpr int LB = M/32;
  int Llow = lane & (LB - 1);
  bool hi = (lane & (LB/2)) != 0;
#pragma unroll
  for (int r = 0; r < 32; r++){
    float px = __shfl_xor_sync(FULLM, sx[r], LB/2);
    float py = __shfl_xor_sync(FULLM, sy[r], LB/2);
    float4 c = __ldg(CT + (M - 2) + r * LB + Llow);
    float ox = sx[r], oy = sy[r];
    float ur = hi ? px : ox, ui = hi ? py : oy;
    float vr = hi ? ox : px, vi = hi ? oy : py;
    sx[r] = c.x*ur - c.y*ui + c.z*vr - c.w*vi;
    sy[r] = c.x*ui + c.y*ur + c.z*vi + c.w*vr;
  }
}

__device__ __forceinline__ float to_tf32_rna(float v){
  float o; asm("cvt.rna.tf32.f32 %0, %1;" : "=f"(o) : "f"(v)); return o;
}

// ---- M generation: run the butterfly network on identity rows (no bias) ----
__global__ void __launch_bounds__(128, 3) mgen_kernel(const float* __restrict__ perm_logit)
{
  int gwarp = (blockIdx.x * blockDim.x + threadIdx.x) >> 5;   // row j = basis index
  int lane  = threadIdx.x & 31;
  if (gwarp >= NSIZE) return;

  float pa[3], pb[3];
#pragma unroll
  for (int j = 0; j < 3; j++){
    pa[j] = 1.0f / (1.0f + __expf(-perm_logit[j]));
    pb[j] = 1.0f / (1.0f + __expf(-perm_logit[3 + j]));
  }

  float sx[32], sy[32], tt[32];
  int hb = gwarp >> 5, lb = gwarp & 31;
#pragma unroll
  for (int r = 0; r < 32; r++) sx[r] = (lane == hb && r == lb) ? 1.0f : 0.0f;

  const float4* C0  = g_coef;
  const float4* C1  = g_coef  + NCOEF;
  const float4* C0T = g_coefT;
  const float4* C1T = g_coefT + NCOEF;

  perm_chain(sx, tt, lane, pa);
  {
    float4 c0 = __ldg(C0 + 0);
    float4 c1 = __ldg(C0 + 1);
#pragma unroll
    for (int g = 0; g < 32; g += 2){
      float x0 = sx[g], x1 = sx[g+1];
      sx[g]   = c0.x*x0 + c0.z*x1;  sy[g]   = c0.y*x0 + c0.w*x1;
      sx[g+1] = c1.x*x0 + c1.z*x1;  sy[g+1] = c1.y*x0 + c1.w*x1;
    }
  }
  diag_local_ip<4 >(sx, sy, C0);
  diag_local_ip<8 >(sx, sy, C0);
  diag_local_ip<16>(sx, sy, C0);
  diag_local_ip<32>(sx, sy, C0);
  diag_shfl_ip<64  >(sx, sy, C0T, lane);
  diag_shfl_ip<128 >(sx, sy, C0T, lane);
  diag_shfl_ip<256 >(sx, sy, C0T, lane);
  diag_shfl_ip<512 >(sx, sy, C0T, lane);
  diag_shfl_ip<1024>(sx, sy, C0T, lane);

  perm_chain(sx, tt, lane, pb);
  perm_chain(sy, tt, lane, pb);

  diag_local_ip<2 >(sx, sy, C1);
  diag_local_ip<4 >(sx, sy, C1);
  diag_local_ip<8 >(sx, sy, C1);
  diag_local_ip<16>(sx, sy, C1);
  diag_local_ip<32>(sx, sy, C1);
  diag_shfl_ip<64  >(sx, sy, C1T, lane);
  diag_shfl_ip<128 >(sx, sy, C1T, lane);
  diag_shfl_ip<256 >(sx, sy, C1T, lane);
  diag_shfl_ip<512 >(sx, sy, C1T, lane);
  diag_shfl_ip<1024>(sx, sy, C1T, lane);

  float* orow = g_M + (size_t)gwarp * NSIZE + lane * 32;
#pragma unroll
  for (int v = 0; v < 8; v++){
    float4 o = make_float4(to_tf32_rna(sx[4*v+0]), to_tf32_rna(sx[4*v+1]),
                           to_tf32_rna(sx[4*v+2]), to_tf32_rna(sx[4*v+3]));
    reinterpret_cast<float4*>(orow)[v] = o;
  }
}

// ---- tf32 GEMM: out[16384,1024] = X[16384,1024] * g_M[1024,1024] + b ----
static constexpr int BM = 128, BN = 128, BK = 16;
static constexpr int LDA = BK + 4;     // 20
static constexpr int LDB = BN + 4;     // 132
static constexpr int NKI = NSIZE / BK; // 64

__global__ void __launch_bounds__(256) gemm_tf32(
    const float* __restrict__ X, const float* __restrict__ bvec, float* __restrict__ out)
{
  __shared__ __align__(16) float pool[2*BM*LDA + 2*BK*LDB];  // 9344 floats = 36.5KB
  float* As0 = pool;
  float* As1 = pool + BM*LDA;
  float* Bs0 = pool + 2*BM*LDA;
  float* Bs1 = pool + 2*BM*LDA + BK*LDB;
  float* Es  = pool;                    // epilogue alias (64*LDB = 8448 <= 9344)

  int tid = threadIdx.x;
  int wid = tid >> 5;
  int wm = wid & 1;         // warp row: 64 rows each
  int wn = wid >> 1;        // warp col: 32 cols each
  int m0 = blockIdx.y * BM;
  int n0 = blockIdx.x * BN;

  wmma::fragment<wmma::accumulator,16,16,8,float> acc[4][2];
#pragma unroll
  for (int fm = 0; fm < 4; fm++)
#pragma unroll
    for (int fn = 0; fn < 2; fn++)
      wmma::fill_fragment(acc[fm][fn], 0.0f);

  // gmem staging registers
  float4 ra[2], rb[2];
  int ar[2], ac4[2], br[2], bc4[2];
#pragma unroll
  for (int i = 0; i < 2; i++){
    int c = tid + i*256;
    ar[i] = c >> 2;  ac4[i] = c & 3;    // A: 128 rows x 4 float4
    br[i] = c >> 5;  bc4[i] = c & 31;   // B: 16 rows x 32 float4
  }

#pragma unroll
  for (int i = 0; i < 2; i++){
    ra[i] = *reinterpret_cast<const float4*>(X + (size_t)(m0 + ar[i]) * NSIZE + ac4[i]*4);
    rb[i] = *reinterpret_cast<const float4*>(g_M + (size_t)br[i] * NSIZE + n0 + bc4[i]*4);
  }
#pragma unroll
  for (int i = 0; i < 2; i++){
    *reinterpret_cast<float4*>(As0 + ar[i]*LDA + ac4[i]*4) = ra[i];
    *reinterpret_cast<float4*>(Bs0 + br[i]*LDB + bc4[i]*4) = rb[i];
  }
  __syncthreads();

  for (int k0 = 0; k0 < NKI; k0++){
    float* Ac = (k0 & 1) ? As1 : As0;
    float* Bc = (k0 & 1) ? Bs1 : Bs0;
    float* An = (k0 & 1) ? As0 : As1;
    float* Bn = (k0 & 1) ? Bs0 : Bs1;

    if (k0 + 1 < NKI){
      int kk = (k0 + 1) * BK;
#pragma unroll
      for (int i = 0; i < 2; i++){
        ra[i] = *reinterpret_cast<const float4*>(X + (size_t)(m0 + ar[i]) * NSIZE + kk + ac4[i]*4);
        rb[i] = *reinterpret_cast<const float4*>(g_M + (size_t)(kk + br[i]) * NSIZE + n0 + bc4[i]*4);
      }
    }

#pragma unroll
    for (int ks = 0; ks < 2; ks++){
      wmma::fragment<wmma::matrix_a,16,16,8,wmma::precision::tf32,wmma::row_major> af[4];
      wmma::fragment<wmma::matrix_b,16,16,8,wmma::precision::tf32,wmma::row_major> bf[2];
#pragma unroll
      for (int fm = 0; fm < 4; fm++)
        wmma::load_matrix_sync(af[fm], Ac + (wm*64 + fm*16)*LDA + ks*8, LDA);
#pragma unroll
      for (int fn = 0; fn < 2; fn++)
        wmma::load_matrix_sync(bf[fn], Bc + (ks*8)*LDB + wn*32 + fn*16, LDB);
#pragma unroll
      for (int fm = 0; fm < 4; fm++)
#pragma unroll
        for (int fn = 0; fn < 2; fn++)
          wmma::mma_sync(acc[fm][fn], af[fm], bf[fn], acc[fm][fn]);
    }

    if (k0 + 1 < NKI){
#pragma unroll
      for (int i = 0; i < 2; i++){
        *reinterpret_cast<float4*>(An + ar[i]*LDA + ac4[i]*4) = ra[i];
        *reinterpret_cast<float4*>(Bn + br[i]*LDB + bc4[i]*4) = rb[i];
      }
      __syncthreads();
    }
  }

  // epilogue: two half-tiles through smem, add bias
#pragma unroll
  for (int phase = 0; phase < 2; phase++){
    __syncthreads();
    if (wm == phase){
#pragma unroll
      for (int fm = 0; fm < 4; fm++)
#pragma unroll
        for (int fn = 0; fn < 2; fn++)
          wmma::store_matrix_sync(Es + (fm*16)*LDB + wn*32 + fn*16, acc[fm][fn], LDB, wmma::mem_row_major);
    }
    __syncthreads();
#pragma unroll
    for (int i = 0; i < 8; i++){
      int c = tid + i*256;        // 64 rows x 32 float4
      int r = c >> 5, c4 = c & 31;
      float4 v  = *reinterpret_cast<float4*>(Es + r*LDB + c4*4);
      float4 bb = __ldg(reinterpret_cast<const float4*>(bvec + n0) + c4);
      v.x += bb.x; v.y += bb.y; v.z += bb.z; v.w += bb.w;
      *reinterpret_cast<float4*>(out + (size_t)(m0 + phase*64 + r) * NSIZE + n0 + c4*4) = v;
    }
  }
}

extern "C" void kernel_launch(void* const* d_in, const int* in_sizes, int n_in,
                              void* d_out, int out_size)
{
  const float* x          = (const float*)d_in[0];
  const float* perm_logit = (const float*)d_in[1];
  const float* abcd       = (const float*)d_in[2];
  const float* b          = (const float*)d_in[3];
  float* out = (float*)d_out;

  repack_kernel<<<(NDEPTH * NCOEF + 255) / 256, 256>>>(abcd);
  mgen_kernel<<<NSIZE / 4, 128>>>(perm_logit);
  dim3 grid(NSIZE / BN, NROWS / BM);   // N fastest: A tiles reused in L2 across N-blocks
  gemm_tf32<<<grid, 256>>>(x, b, out);
}

// round 10
// speedup vs baseline: 2.0496x; 2.0496x over previous
#include <cuda_runtime.h>
#include <cstdint>

#define FULLM 0xFFFFFFFFu
static constexpr int NDEPTH = 2;
static constexpr int NSIZE  = 1024;
static constexpr int NROWS  = 16384;
static constexpr int NCOEF  = 2046;

__device__ float4 g_coef [NDEPTH * NCOEF];
__device__ float4 g_coefT[NDEPTH * NCOEF];
__device__ float  g_Mt[NSIZE * NSIZE];            // Mt[n][k] = M[k][n], tf32-rna
__device__ float  g_Xr[(size_t)NROWS * NSIZE];    // X rounded to tf32 (rna)

// ===================== butterfly machinery (proven) =====================
__global__ void repack_kernel(const float* __restrict__ abcd){
  int idx = blockIdx.x * blockDim.x + threadIdx.x;
  if (idx >= NDEPTH * NCOEF) return;
  int d  = idx / NCOEF;
  int qg = idx - d * NCOEF;
  int v  = qg + 2;
  int m  = 1 << (31 - __clz(v));
  int q  = v - m;
  int off = 4096 - 4 * m;
  int half = m >> 1;
  int ih = (q >= half) ? 1 : 0;
  int k  = q - ih * half;
  const float* base = abcd + (size_t)d * 4092 * 2;
  int i0 = off + ih * m + k;
  int i1 = i0 + half;
  float4 val = make_float4(base[2*i0], base[2*i0+1], base[2*i1], base[2*i1+1]);
  g_coef[idx] = val;
  int LB = m / 32;
  int tpos = (m >= 64) ? ((q & 31) * LB + (q >> 5)) : q;
  g_coefT[d * NCOEF + (m - 2) + tpos] = val;
}

__device__ __forceinline__ float mixf(float a, float b, float p){ return fmaf(p, b - a, a); }

template<int M>
__device__ __forceinline__ void perm_local(float* s, float* t, float p0, float p1, float p2){
#pragma unroll
  for (int g = 0; g < 32; g += M)
#pragma unroll
    for (int j = 0; j < M; j++){
      int sj = (j < M/2) ? 2*j : 2*j - M + 1;
      t[g+j] = mixf(s[g+j], s[g+sj], p0);
    }
#pragma unroll
  for (int g = 0; g < 32; g += M)
#pragma unroll
    for (int j = 0; j < M; j++){
      int pj = (j & (M/2)) | ((M/2 - 1) & ~j);
      s[g+j] = mixf(t[g+j], t[g+pj], (j < M/2) ? p1 : p2);
    }
}

template<int M>
__device__ __forceinline__ void perm_shfl_1(float* s, float* t, int lane, float p0, float p1, float p2){
  constexpr int LB = M/32;
  constexpr int T  = M/64;
  int Llow = lane & (LB - 1);
  int msb  = (Llow & T) ? 1 : 0;
  int slb  = (lane & ~(LB - 1)) | (2 * (Llow & (T - 1)));
  int sl0  = slb + msb;
  int sl1  = slb + 1 - msb;
  bool le  = (lane & 1) == 0;
#pragma unroll
  for (int k = 0; k < 16; k++){
    const int e = (2*k) & 31;
    float u1 = le ? s[e] : s[e|1];
    float v1 = (M == 64) ? u1 : __shfl_sync(FULLM, u1, sl0);
    float u2 = le ? s[e|1] : s[e];
    float v2 = __shfl_sync(FULLM, u2, sl1);
    float a = msb ? v2 : v1;
    float b = msb ? v1 : v2;
    t[k]    = mixf(s[k],    a, p0);
    t[k+16] = mixf(s[k+16], b, p0);
  }
  constexpr int RM = T - 1;
  float ps = (lane & T) ? p2 : p1;
  if (RM == 0){
#pragma unroll
    for (int r = 0; r < 16; r++){
      float x0 = t[r], x1 = t[31-r];
      s[r]    = mixf(x0, x1, ps);
      s[31-r] = mixf(x1, x0, ps);
    }
  } else {
#pragma unroll
    for (int r = 0; r < 32; r++){
      float pv = __shfl_xor_sync(FULLM, t[31-r], RM);
      s[r] = mixf(t[r], pv, ps);
    }
  }
}

__device__ __forceinline__ void perm_chain(float* s, float* t, int lane, const float* p){
  perm_local<4 >(s, t, p[0], p[1], p[2]);
  perm_local<8 >(s, t, p[0], p[1], p[2]);
  perm_local<16>(s, t, p[0], p[1], p[2]);
  perm_local<32>(s, t, p[0], p[1], p[2]);
  perm_shfl_1<64  >(s, t, lane, p[0], p[1], p[2]);
  perm_shfl_1<128 >(s, t, lane, p[0], p[1], p[2]);
  perm_shfl_1<256 >(s, t, lane, p[0], p[1], p[2]);
  perm_shfl_1<512 >(s, t, lane, p[0], p[1], p[2]);
  perm_shfl_1<1024>(s, t, lane, p[0], p[1], p[2]);
}

template<int M>
__device__ __forceinline__ void diag_local_ip(float* sx, float* sy, const float4* __restrict__ C){
#pragma unroll
  for (int q = 0; q < M/2; q++){
    float4 clo = __ldg(C + (M - 2) + q);
    float4 chi = __ldg(C + (M - 2) + q + M/2);
#pragma unroll
    for (int g = 0; g < 32; g += M){
      int lo = g + q, hi = lo + M/2;
      float ur = sx[lo], ui = sy[lo], vr = sx[hi], vi = sy[hi];
      sx[lo] = clo.x*ur - clo.y*ui + clo.z*vr - clo.w*vi;
      sy[lo] = clo.x*ui + clo.y*ur + clo.z*vi + clo.w*vr;
      sx[hi] = chi.x*ur - chi.y*ui + chi.z*vr - chi.w*vi;
      sy[hi] = chi.x*ui + chi.y*ur + chi.z*vi + chi.w*vr;
    }
  }
}

template<int M>
__device__ __forceinline__ void diag_shfl_ip(float* sx, float* sy, const float4* __restrict__ CT, int lane){
  constexpr int LB = M/32;
  int Llow = lane & (LB - 1);
  bool hi = (lane & (LB/2)) != 0;
#pragma unroll
  for (int r = 0; r < 32; r++){
    float px = __shfl_xor_sync(FULLM, sx[r], LB/2);
    float py = __shfl_xor_sync(FULLM, sy[r], LB/2);
    float4 c = __ldg(CT + (M - 2) + r * LB + Llow);
    float ox = sx[r], oy = sy[r];
    float ur = hi ? px : ox, ui = hi ? py : oy;
    float vr = hi ? ox : px, vi = hi ? oy : py;
    sx[r] = c.x*ur - c.y*ui + c.z*vr - c.w*vi;
    sy[r] = c.x*ui + c.y*ur + c.z*vi + c.w*vr;
  }
}

__device__ __forceinline__ float to_tf32_rna(float v){
  float o; asm("cvt.rna.tf32.f32 %0, %1;" : "=f"(o) : "f"(v)); return o;
}

// ---- M generation on identity rows; writes TRANSPOSED Mt[n][k], tf32-rna ----
__global__ void __launch_bounds__(128, 3) mgen_kernel(const float* __restrict__ perm_logit)
{
  int gwarp = (blockIdx.x * blockDim.x + threadIdx.x) >> 5;   // basis index j (= k dim)
  int lane  = threadIdx.x & 31;
  if (gwarp >= NSIZE) return;

  float pa[3], pb[3];
#pragma unroll
  for (int j = 0; j < 3; j++){
    pa[j] = 1.0f / (1.0f + __expf(-perm_logit[j]));
    pb[j] = 1.0f / (1.0f + __expf(-perm_logit[3 + j]));
  }

  float sx[32], sy[32], tt[32];
  int hb = gwarp >> 5, lb = gwarp & 31;
#pragma unroll
  for (int r = 0; r < 32; r++) sx[r] = (lane == hb && r == lb) ? 1.0f : 0.0f;

  const float4* C0  = g_coef;
  const float4* C1  = g_coef  + NCOEF;
  const float4* C0T = g_coefT;
  const float4* C1T = g_coefT + NCOEF;

  perm_chain(sx, tt, lane, pa);
  {
    float4 c0 = __ldg(C0 + 0);
    float4 c1 = __ldg(C0 + 1);
#pragma unroll
    for (int g = 0; g < 32; g += 2){
      float x0 = sx[g], x1 = sx[g+1];
      sx[g]   = c0.x*x0 + c0.z*x1;  sy[g]   = c0.y*x0 + c0.w*x1;
      sx[g+1] = c1.x*x0 + c1.z*x1;  sy[g+1] = c1.y*x0 + c1.w*x1;
    }
  }
  diag_local_ip<4 >(sx, sy, C0);
  diag_local_ip<8 >(sx, sy, C0);
  diag_local_ip<16>(sx, sy, C0);
  diag_local_ip<32>(sx, sy, C0);
  diag_shfl_ip<64  >(sx, sy, C0T, lane);
  diag_shfl_ip<128 >(sx, sy, C0T, lane);
  diag_shfl_ip<256 >(sx, sy, C0T, lane);
  diag_shfl_ip<512 >(sx, sy, C0T, lane);
  diag_shfl_ip<1024>(sx, sy, C0T, lane);

  perm_chain(sx, tt, lane, pb);
  perm_chain(sy, tt, lane, pb);

  diag_local_ip<2 >(sx, sy, C1);
  diag_local_ip<4 >(sx, sy, C1);
  diag_local_ip<8 >(sx, sy, C1);
  diag_local_ip<16>(sx, sy, C1);
  diag_local_ip<32>(sx, sy, C1);
  diag_shfl_ip<64  >(sx, sy, C1T, lane);
  diag_shfl_ip<128 >(sx, sy, C1T, lane);
  diag_shfl_ip<256 >(sx, sy, C1T, lane);
  diag_shfl_ip<512 >(sx, sy, C1T, lane);
  diag_shfl_ip<1024>(sx, sy, C1T, lane);

  // scatter transposed: Mt[i][j], i = lane*32 + r (output idx), j = gwarp (basis)
#pragma unroll
  for (int r = 0; r < 32; r++)
    g_Mt[(size_t)(lane * 32 + r) * NSIZE + gwarp] = to_tf32_rna(sx[r]);
}

// ---- X -> tf32-rna copy (kills truncation bias in the MMA) ----
__global__ void xround_kernel(const float* __restrict__ x){
  size_t i = (size_t)blockIdx.x * blockDim.x + threadIdx.x;
  float4 v = __ldg(reinterpret_cast<const float4*>(x) + i);
  v.x = to_tf32_rna(v.x); v.y = to_tf32_rna(v.y);
  v.z = to_tf32_rna(v.z); v.w = to_tf32_rna(v.w);
  reinterpret_cast<float4*>(g_Xr)[i] = v;
}

// ===================== tf32 mma.sync GEMM =====================
// out[16384,1024] = Xr * M + b. D[m,n] = sum_k A[m,k]*B[k,n], B[k][n] = Mt[n][k].
// 128x128x32 CTA tile, 4 warps (64x64 warp tile), 3-stage cp.async, XOR-swizzled smem.
static constexpr int BK = 32, NK2 = NSIZE / BK, S = 3;
static constexpr int TILE_FLOATS = 128 * 32;            // 4096 floats = 16KB
static constexpr int STAGE_FLOATS = 2 * TILE_FLOATS;    // A then B
static constexpr int GSMEM_TOTAL = S * STAGE_FLOATS * 4; // 96KB

#define CP_ASYNC16(dst, src) \
  asm volatile("cp.async.cg.shared.global [%0], [%1], 16;" :: "r"(dst), "l"(src) : "memory")
#define CP_ASYNC_COMMIT() asm volatile("cp.async.commit_group;" ::: "memory")
#define CP_ASYNC_WAIT1()  asm volatile("cp.async.wait_group 1;" ::: "memory")

__device__ __forceinline__ uint32_t smem_u32(const void* p){
  uint32_t a;
  asm("{ .reg .u64 t; cvta.to.shared.u64 t, %1; cvt.u32.u64 %0, t; }" : "=r"(a) : "l"(p));
  return a;
}

__device__ __forceinline__ void mma_tf32(float* d, const uint32_t* a, const uint32_t* b){
  asm volatile("mma.sync.aligned.m16n8k8.row.col.f32.tf32.tf32.f32 "
    "{%0,%1,%2,%3}, {%4,%5,%6,%7}, {%8,%9}, {%0,%1,%2,%3};"
    : "+f"(d[0]), "+f"(d[1]), "+f"(d[2]), "+f"(d[3])
    : "r"(a[0]), "r"(a[1]), "r"(a[2]), "r"(a[3]), "r"(b[0]), "r"(b[1]));
}

// swizzled float index within a 128x32 tile: row r, float col c
__device__ __forceinline__ int swz(int r, int c){
  return r * 32 + ((((c >> 2) ^ (r & 7)) << 2) | (c & 3));
}

__device__ __forceinline__ void load_stage(uint32_t Ab, uint32_t Bb, int j, int m0, int n0, int tid){
  int rb = tid >> 3;          // 0..15
  int c4 = tid & 7;           // 16B chunk
  const float* Asrc = g_Xr + (size_t)m0 * NSIZE + j * BK + c4 * 4;
  const float* Bsrc = g_Mt + (size_t)n0 * NSIZE + j * BK + c4 * 4;
#pragma unroll
  for (int pass = 0; pass < 8; pass++){
    int r = pass * 16 + rb;
    uint32_t soff = (uint32_t)(r * 128 + ((c4 ^ (r & 7)) << 4));
    CP_ASYNC16(Ab + soff, Asrc + (size_t)r * NSIZE);
    CP_ASYNC16(Bb + soff, Bsrc + (size_t)r * NSIZE);
  }
}

__global__ void __launch_bounds__(128, 2) gemm_mma(const float* __restrict__ bvec,
                                                   float* __restrict__ out)
{
  extern __shared__ __align__(128) float smem[];
  uint32_t sb = smem_u32(smem);
  int tid = threadIdx.x, wid = tid >> 5, lane = tid & 31;
  int g  = lane >> 2;      // group id (0..7)
  int tg = lane & 3;       // thread in group
  int wm = wid & 1;        // warp m-half (64 rows)
  int wn = wid >> 1;       // warp n-half (64 cols)
  int n0 = blockIdx.x * 128;
  int m0 = blockIdx.y * 128;

  uint32_t Ab[S], Bb[S];
#pragma unroll
  for (int s = 0; s < S; s++){
    Ab[s] = sb + s * STAGE_FLOATS * 4;
    Bb[s] = Ab[s] + TILE_FLOATS * 4;
  }

  float acc[4][8][4];
#pragma unroll
  for (int mt = 0; mt < 4; mt++)
#pragma unroll
    for (int nt = 0; nt < 8; nt++)
#pragma unroll
      for (int i = 0; i < 4; i++) acc[mt][nt][i] = 0.0f;

  // prologue: stages 0,1
  load_stage(Ab[0], Bb[0], 0, m0, n0, tid); CP_ASYNC_COMMIT();
  load_stage(Ab[1], Bb[1], 1, m0, n0, tid); CP_ASYNC_COMMIT();

  for (int j = 0; j < NK2; j++){
    CP_ASYNC_WAIT1();
    __syncthreads();
    int jn = j + 2;
    if (jn < NK2){
      int sn = jn % S;
      load_stage(Ab[sn], Bb[sn], jn, m0, n0, tid);
    }
    CP_ASYNC_COMMIT();

    int st = j % S;
    const float* As = smem + st * STAGE_FLOATS;
    const float* Bs = As + TILE_FLOATS;
#pragma unroll
    for (int ks = 0; ks < 4; ks++){
      uint32_t af[4][4], bf[8][2];
      int co0 = ((((2*ks) ^ g) << 2) | tg);
      int co1 = co0 ^ 4;
#pragma unroll
      for (int mt = 0; mt < 4; mt++){
        int r0 = wm*64 + mt*16 + g;
        af[mt][0] = __float_as_uint(As[r0*32      + co0]);
        af[mt][1] = __float_as_uint(As[(r0+8)*32  + co0]);
        af[mt][2] = __float_as_uint(As[r0*32      + co1]);
        af[mt][3] = __float_as_uint(As[(r0+8)*32  + co1]);
      }
#pragma unroll
      for (int nt = 0; nt < 8; nt++){
        int n = wn*64 + nt*8 + g;
        bf[nt][0] = __float_as_uint(Bs[n*32 + co0]);
        bf[nt][1] = __float_as_uint(Bs[n*32 + co1]);
      }
#pragma unroll
      for (int mt = 0; mt < 4; mt++)
#pragma unroll
        for (int nt = 0; nt < 8; nt++)
          mma_tf32(acc[mt][nt], af[mt], bf[nt]);
    }
  }

  // epilogue: direct register -> gmem, add bias
#pragma unroll
  for (int nt = 0; nt < 8; nt++){
    int n = n0 + wn*64 + nt*8 + 2*tg;
    float2 bb = __ldg(reinterpret_cast<const float2*>(bvec + n));
#pragma unroll
    for (int mt = 0; mt < 4; mt++){
      int r0 = m0 + wm*64 + mt*16 + g;
      float2 v0 = make_float2(acc[mt][nt][0] + bb.x, acc[mt][nt][1] + bb.y);
      float2 v1 = make_float2(acc[mt][nt][2] + bb.x, acc[mt][nt][3] + bb.y);
      *reinterpret_cast<float2*>(out + (size_t)r0 * NSIZE + n)       = v0;
      *reinterpret_cast<float2*>(out + (size_t)(r0+8) * NSIZE + n)   = v1;
    }
  }
}

// ===================== launch =====================
extern "C" void kernel_launch(void* const* d_in, const int* in_sizes, int n_in,
                              void* d_out, int out_size)
{
  const float* x          = (const float*)d_in[0];
  const float* perm_logit = (const float*)d_in[1];
  const float* abcd       = (const float*)d_in[2];
  const float* b          = (const float*)d_in[3];
  float* out = (float*)d_out;

  repack_kernel<<<(NDEPTH * NCOEF + 255) / 256, 256>>>(abcd);
  mgen_kernel<<<NSIZE / 4, 128>>>(perm_logit);
  xround_kernel<<<(NROWS * (NSIZE/4)) / 256, 256>>>(x);

  cudaFuncSetAttribute(gemm_mma, cudaFuncAttributeMaxDynamicSharedMemorySize, GSMEM_TOTAL);
  dim3 grid(NSIZE / 128, NROWS / 128);   // n fastest: consecutive CTAs share X slab in L2
  gemm_mma<<<grid, 128, GSMEM_TOTAL>>>(b, out);
}